// round 5
// baseline (speedup 1.0000x reference)
#include <cuda_runtime.h>
#include <cstdint>

#define TT 2048
#define BB 32
#define NN 1024
#define NCH 32          // t-chunks of 64

// ---------------- scratch (device globals; no allocation allowed) ----------
__device__ float g_apart[8u  * BB * NN];    // split-K partials, first GEMM
__device__ float g_fpart[16u * BB * NN];    // split-K partials, final GEMM
__device__ float g_cpart[(size_t)NCH * BB * NN]; // chunked content partials
__device__ float g_lmax [BB * NCH];         // per-(b,chunk) local max
__device__ float g_lsum [BB * NCH];         // per-(b,chunk) local exp-sum
__device__ float g_content[BB * NN];

__device__ __forceinline__ float fast_tanh(float x) {
    float e = __expf(2.0f * x);
    return 1.0f - __fdividef(2.0f, e + 1.0f);
}

// ---------------------------------------------------------------------------
// Split-K GEMM: part[kchunk][b][n] = sum_{k in chunk} S[b][k] * W[n][k]
// which=0: S = hx (K=NN) -> g_apart.   which=1: S = [g_content|hx] -> g_fpart.
// g_content only referenced in device code (host-side __device__ symbol args
// bind the zero ATS host shadow on GB300).
// ---------------------------------------------------------------------------
__global__ __launch_bounds__(256) void gemm32_partial(
    const float* __restrict__ hx,
    const float* __restrict__ W, int K, int which)
{
    __shared__ float sS[128 * 34];
    __shared__ float sW[128 * 34];
    const int tid = threadIdx.x;
    const int n0  = blockIdx.x * 32;
    const int k0  = blockIdx.y * 128;

    #pragma unroll
    for (int p = 0; p < 16; p++) {
        int i = tid + p * 256;          // 32 b x 128 k
        int b = i >> 7, c = i & 127;
        int kg = k0 + c;
        float val;
        if (which == 0)       val = hx[b * NN + kg];
        else if (kg < NN)     val = g_content[b * NN + kg];
        else                  val = hx[b * NN + kg - NN];
        sS[c * 34 + b] = val;
    }
    #pragma unroll
    for (int p = 0; p < 16; p++) {
        int i = tid + p * 256;          // 32 n x 128 k
        int nl = i >> 7, c = i & 127;
        sW[c * 34 + nl] = W[(size_t)(n0 + nl) * K + k0 + c];
    }
    __syncthreads();

    const int b0  = (tid & 15) * 2;
    const int nl0 = (tid >> 4) * 2;
    float a00 = 0.f, a01 = 0.f, a10 = 0.f, a11 = 0.f;
    #pragma unroll 8
    for (int k = 0; k < 128; k++) {
        float2 d = *(const float2*)&sS[k * 34 + b0];
        float2 w = *(const float2*)&sW[k * 34 + nl0];
        a00 += d.x * w.x;  a01 += d.x * w.y;
        a10 += d.y * w.x;  a11 += d.y * w.y;
    }

    float* part = (which ? g_fpart : g_apart) + (size_t)blockIdx.y * (BB * NN);
    part[(b0 + 0) * NN + n0 + nl0 + 0] = a00;
    part[(b0 + 0) * NN + n0 + nl0 + 1] = a01;
    part[(b0 + 1) * NN + n0 + nl0 + 0] = a10;
    part[(b0 + 1) * NN + n0 + nl0 + 1] = a11;
}

// ---------------------------------------------------------------------------
// Fused stream kernel (chunked softmax). Block = (chunk ch, batch b), 64 t.
//  A) scores for its 64 t from ef (+ fused dec combine)
//  B) local max/sum, weights w_t = exp(s_t - m_ch) * mask_t (sum unmasked)
//  C) weighted accumulate of eo chunk -> g_cpart[ch][b][:]
// ---------------------------------------------------------------------------
__global__ __launch_bounds__(256) void fused_stream_kernel(
    const float* __restrict__ ef, const float* __restrict__ eo,
    const float* __restrict__ mask,
    const float* __restrict__ vw, const float* __restrict__ vb,
    const float* __restrict__ Ws_b)
{
    const int b   = blockIdx.y;
    const int ch  = blockIdx.x;
    const int t0  = ch * 64;
    const int tid = threadIdx.x;
    const int warp = tid >> 5, lane = tid & 31;

    __shared__ float sred[16 * 256];
    __shared__ float s_scores[64];
    __shared__ float s_w[64];
    __shared__ float s_m, s_sum;

    // dec[b,:] = Ws_b + sum of 8 split-K partials (L2-resident)
    float4 d = reinterpret_cast<const float4*>(Ws_b)[tid];
    #pragma unroll
    for (int c = 0; c < 8; c++) {
        float4 p = reinterpret_cast<const float4*>(g_apart + c * (BB * NN) + b * NN)[tid];
        d.x += p.x; d.y += p.y; d.z += p.z; d.w += p.w;
    }
    float4 v = reinterpret_cast<const float4*>(vw)[tid];
    const float vbias = vb[0];

    // Phase A: 4 sub-batches of 16 t-rows
    #pragma unroll
    for (int sb = 0; sb < 4; sb++) {
        float pr[16];
        #pragma unroll
        for (int r = 0; r < 16; r++) {
            size_t row = ((size_t)(t0 + sb * 16 + r) * BB + b) * NN;
            float4 x = reinterpret_cast<const float4*>(ef + row)[tid];
            pr[r] = fast_tanh(x.x + d.x) * v.x
                  + fast_tanh(x.y + d.y) * v.y
                  + fast_tanh(x.z + d.z) * v.z
                  + fast_tanh(x.w + d.w) * v.w;
        }
        #pragma unroll
        for (int r = 0; r < 16; r++) sred[r * 256 + tid] = pr[r];
        __syncthreads();
        #pragma unroll
        for (int rr = 0; rr < 2; rr++) {
            int r = warp * 2 + rr;
            float s = 0.f;
            #pragma unroll
            for (int j = 0; j < 8; j++) s += sred[r * 256 + lane + 32 * j];
            #pragma unroll
            for (int o = 16; o; o >>= 1) s += __shfl_xor_sync(0xffffffffu, s, o);
            if (lane == 0) s_scores[sb * 16 + r] = s + vbias;
        }
        __syncthreads();
    }

    // Phase B: local max / sum (warp 0), weights (2 warps)
    if (warp == 0) {
        float a0 = s_scores[lane], a1 = s_scores[lane + 32];
        float m = fmaxf(a0, a1);
        #pragma unroll
        for (int o = 16; o; o >>= 1) m = fmaxf(m, __shfl_xor_sync(0xffffffffu, m, o));
        float ssum = __expf(a0 - m) + __expf(a1 - m);
        #pragma unroll
        for (int o = 16; o; o >>= 1) ssum += __shfl_xor_sync(0xffffffffu, ssum, o);
        if (lane == 0) {
            s_m = m;  s_sum = ssum;
            g_lmax[b * NCH + ch] = m;
            g_lsum[b * NCH + ch] = ssum;
        }
    }
    __syncthreads();
    if (tid < 64)
        s_w[tid] = __expf(s_scores[tid] - s_m) * mask[b * TT + t0 + tid];
    __syncthreads();

    // Phase C: weighted accumulate of eo chunk
    float4 acc = make_float4(0.f, 0.f, 0.f, 0.f);
    size_t base = (((size_t)t0) * BB + b) * NN;
    #pragma unroll 4
    for (int r = 0; r < 64; r++) {
        float a = s_w[r];
        float4 x = reinterpret_cast<const float4*>(eo + base + (size_t)r * BB * NN)[tid];
        acc.x += a * x.x;  acc.y += a * x.y;
        acc.z += a * x.z;  acc.w += a * x.w;
    }
    reinterpret_cast<float4*>(g_cpart + ((size_t)ch * BB + b) * NN)[tid] = acc;
}

// ---------------------------------------------------------------------------
// Finalize: content[b,n] = sum_ch exp(m_ch - M_b) * cpart[ch][b][n] / denom_b
// denom_b = sum_ch lsum_ch * exp(m_ch - M_b). Grid 128 (4 blocks per b).
// ---------------------------------------------------------------------------
__global__ __launch_bounds__(256) void finalize_content_kernel()
{
    const int b  = blockIdx.x >> 2;
    const int n0 = (blockIdx.x & 3) * 256;
    const int tid = threadIdx.x;
    __shared__ float sc[NCH];

    if (tid < 32) {
        float m_l = g_lmax[b * NCH + tid];
        float M = m_l;
        #pragma unroll
        for (int o = 16; o; o >>= 1) M = fmaxf(M, __shfl_xor_sync(0xffffffffu, M, o));
        float e = __expf(m_l - M);
        float den = g_lsum[b * NCH + tid] * e;
        #pragma unroll
        for (int o = 16; o; o >>= 1) den += __shfl_xor_sync(0xffffffffu, den, o);
        sc[tid] = e / den;
    }
    __syncthreads();

    const int i = b * NN + n0 + tid;
    float s = 0.f;
    #pragma unroll
    for (int c = 0; c < NCH; c++) s += sc[c] * g_cpart[(size_t)c * (BB * NN) + i];
    g_content[i] = s;
}

// out = tanh(sum of 16 k-chunk partials + lin_b)
__global__ __launch_bounds__(256) void combine_out(
    const float* __restrict__ lin_b, float* __restrict__ out)
{
    int i = blockIdx.x * 256 + threadIdx.x;
    float s = lin_b[i & (NN - 1)];
    #pragma unroll
    for (int c = 0; c < 16; c++) s += g_fpart[c * (BB * NN) + i];
    out[i] = fast_tanh(s);
}

// ---------------------------------------------------------------------------
extern "C" void kernel_launch(void* const* d_in, const int* in_sizes, int n_in,
                              void* d_out, int out_size)
{
    const float* decoder_hx      = (const float*)d_in[0];
    const float* encoder_outputs = (const float*)d_in[1];
    const float* encoder_feature = (const float*)d_in[2];
    const float* mask_tensor     = (const float*)d_in[3];
    const float* Ws_w            = (const float*)d_in[4];
    const float* Ws_b            = (const float*)d_in[5];
    const float* v_w             = (const float*)d_in[6];
    const float* v_b             = (const float*)d_in[7];
    const float* lin_w           = (const float*)d_in[8];
    const float* lin_b           = (const float*)d_in[9];
    float* out = (float*)d_out;

    // 1) dec_feature split-K partials (combine fused into stream kernel)
    gemm32_partial<<<dim3(NN / 32, 8), 256>>>(decoder_hx, Ws_w, NN, 0);

    // 2) fused scores + chunked-softmax + content (streams 512MB, one launch)
    fused_stream_kernel<<<dim3(NCH, BB), 256>>>(
        encoder_feature, encoder_outputs, mask_tensor, v_w, v_b, Ws_b);

    // 3) combine chunks with global softmax correction
    finalize_content_kernel<<<128, 256>>>();

    // 4) out = tanh([content|hx] @ lin_w^T + lin_b)
    gemm32_partial<<<dim3(NN / 32, 16), 256>>>(decoder_hx, lin_w, 2 * NN, 1);
    combine_out<<<(BB * NN) / 256, 256>>>(lin_b, out);

    (void)in_sizes; (void)n_in; (void)out_size;
}